// round 1
// baseline (speedup 1.0000x reference)
#include <cuda_runtime.h>

#define NTOK 4096
#define HID 256
#define NHEADS 8
#define HD 32
#define EPSBN 1e-5f
#define QSCALE 0.17677669529663687f   // 1/sqrt(32)

// ------------------- scratch (device globals; no allocation) -------------------
__device__ float g_Qf[NTOK * HID];
__device__ float g_Kf[NTOK * HID];
__device__ float g_Vf[NTOK * HID];
__device__ float g_AO[NTOK * HID];    // attention output (flat reshape layout)
__device__ float g_X[NTOK * HID];     // after O-proj
__device__ float g_X1[NTOK * HID];    // after BN1
__device__ float g_Mid[NTOK * 2 * HID];
__device__ float g_F[NTOK * HID];     // FFN output
__device__ float g_psum[16 * HID];
__device__ float g_psq[16 * HID];
__device__ float g_mean[HID];
__device__ float g_rstd[HID];

// ------------------- generic SGEMM: C = (A[M,K] @ B[N,K]^T + bias) * scale -------------------
__global__ void gemm_nt(const float* __restrict__ A, const float* __restrict__ B,
                        const float* __restrict__ bias, float* __restrict__ C,
                        int M, int Nn, int K, float scale, int relu)
{
    __shared__ float As[64][33];
    __shared__ float Bs[64][33];
    int i0 = blockIdx.y * 64, j0 = blockIdx.x * 64;
    int tid = threadIdx.x;
    int ty = tid >> 4, tx = tid & 15;
    float acc[4][4] = {};
    for (int kk = 0; kk < K; kk += 32) {
        #pragma unroll
        for (int i = tid; i < 2048; i += 256) {
            int r = i >> 5, c = i & 31;
            As[r][c] = A[(size_t)(i0 + r) * K + kk + c];
            Bs[r][c] = B[(size_t)(j0 + r) * K + kk + c];
        }
        __syncthreads();
        #pragma unroll
        for (int k = 0; k < 32; k++) {
            float a[4], b[4];
            #pragma unroll
            for (int u = 0; u < 4; u++) a[u] = As[ty * 4 + u][k];
            #pragma unroll
            for (int v = 0; v < 4; v++) b[v] = Bs[tx * 4 + v][k];
            #pragma unroll
            for (int u = 0; u < 4; u++)
                #pragma unroll
                for (int v = 0; v < 4; v++) acc[u][v] += a[u] * b[v];
        }
        __syncthreads();
    }
    #pragma unroll
    for (int u = 0; u < 4; u++)
        #pragma unroll
        for (int v = 0; v < 4; v++) {
            int i = i0 + ty * 4 + u, j = j0 + tx * 4 + v;
            float cv = (acc[u][v] + bias[j]) * scale;
            if (relu) cv = fmaxf(cv, 0.f);
            C[(size_t)i * Nn + j] = cv;
        }
}

// ------------------- flash attention with multiplicative adjacency -------------------
// grid: (NTOK/64, NHEADS), 256 threads.
// q,k,v flat layout: [head][n][d] at h*NTOK*32 + n*32 + d (raw reshape of [N,256]).
__global__ void flash_attn(const float* __restrict__ Qf, const float* __restrict__ Kf,
                           const float* __restrict__ Vf, const float* __restrict__ Amat,
                           float* __restrict__ Of)
{
    __shared__ float qs[64][33];
    __shared__ float ks[64][33];
    __shared__ float vs[64][33];
    __shared__ float Ss[64][65];
    __shared__ float m_s[64], l_s[64], alpha_s[64];

    int hh = blockIdx.y;
    int row0 = blockIdx.x * 64;
    int tid = threadIdx.x;

    const float* qbase = Qf + (size_t)hh * NTOK * HD;
    const float* kbase = Kf + (size_t)hh * NTOK * HD;
    const float* vbase = Vf + (size_t)hh * NTOK * HD;

    // load q tile [64][32] (contiguous)
    #pragma unroll
    for (int i = tid; i < 64 * 32; i += 256) {
        int r = i >> 5, c = i & 31;
        qs[r][c] = qbase[(size_t)row0 * HD + i];
    }
    if (tid < 64) { m_s[tid] = -3.0e38f; l_s[tid] = 0.f; }

    // step-A mapping
    int ty = tid >> 4, tx = tid & 15;
    // step-B mapping
    int brow = tid >> 2, bsub = tid & 3;
    // step-C mapping: 2 rows x 4 cols per thread
    int rg = tid >> 3, dg = tid & 7;
    int r0c = rg * 2, d0 = dg * 4;
    float acc[2][4] = {};

    for (int mt = 0; mt < NTOK / 64; mt++) {
        int m0 = mt * 64;
        __syncthreads();  // protect smem reuse from previous iteration
        #pragma unroll
        for (int i = tid; i < 64 * 32; i += 256) {
            int r = i >> 5, c = i & 31;
            ks[r][c] = kbase[(size_t)m0 * HD + i];
            vs[r][c] = vbase[(size_t)m0 * HD + i];
        }
        __syncthreads();

        // step A: S[n][m] = (q·k) * A[row0+n][m0+m]
        {
            float sacc[4][4] = {};
            #pragma unroll
            for (int d = 0; d < HD; d++) {
                float qa[4], kb[4];
                #pragma unroll
                for (int u = 0; u < 4; u++) qa[u] = qs[ty * 4 + u][d];
                #pragma unroll
                for (int v = 0; v < 4; v++) kb[v] = ks[tx * 4 + v][d];
                #pragma unroll
                for (int u = 0; u < 4; u++)
                    #pragma unroll
                    for (int v = 0; v < 4; v++) sacc[u][v] += qa[u] * kb[v];
            }
            #pragma unroll
            for (int u = 0; u < 4; u++)
                #pragma unroll
                for (int v = 0; v < 4; v++) {
                    int n = ty * 4 + u, m = tx * 4 + v;
                    float aval = Amat[(size_t)(row0 + n) * NTOK + m0 + m];
                    Ss[n][m] = sacc[u][v] * aval;
                }
        }
        __syncthreads();

        // step B: online softmax (4 threads per row, 16 cols each)
        {
            float vreg[16];
            float tmax = -3.0e38f;
            #pragma unroll
            for (int j = 0; j < 16; j++) {
                vreg[j] = Ss[brow][bsub * 16 + j];
                tmax = fmaxf(tmax, vreg[j]);
            }
            tmax = fmaxf(tmax, __shfl_xor_sync(0xffffffff, tmax, 1));
            tmax = fmaxf(tmax, __shfl_xor_sync(0xffffffff, tmax, 2));
            float mold = m_s[brow];
            float mnew = fmaxf(mold, tmax);
            float lsum = 0.f;
            #pragma unroll
            for (int j = 0; j < 16; j++) {
                float p = __expf(vreg[j] - mnew);
                Ss[brow][bsub * 16 + j] = p;
                lsum += p;
            }
            lsum += __shfl_xor_sync(0xffffffff, lsum, 1);
            lsum += __shfl_xor_sync(0xffffffff, lsum, 2);
            if (bsub == 0) {
                float al = __expf(mold - mnew);
                l_s[brow] = l_s[brow] * al + lsum;
                m_s[brow] = mnew;
                alpha_s[brow] = al;
            }
        }
        __syncthreads();

        // step C: o += P @ V  (each thread: 2 rows x 4 dims)
        {
            float al0 = alpha_s[r0c], al1 = alpha_s[r0c + 1];
            #pragma unroll
            for (int j = 0; j < 4; j++) { acc[0][j] *= al0; acc[1][j] *= al1; }
            #pragma unroll
            for (int m = 0; m < 64; m++) {
                float p0 = Ss[r0c][m], p1 = Ss[r0c + 1][m];
                #pragma unroll
                for (int j = 0; j < 4; j++) {
                    float vv = vs[m][d0 + j];
                    acc[0][j] += p0 * vv;
                    acc[1][j] += p1 * vv;
                }
            }
        }
    }

    __syncthreads();
    float inv0 = 1.f / l_s[r0c];
    float inv1 = 1.f / l_s[r0c + 1];
    size_t obase = (size_t)hh * NTOK * HD;
    #pragma unroll
    for (int j = 0; j < 4; j++) {
        Of[obase + (size_t)(row0 + r0c) * HD + d0 + j] = acc[0][j] * inv0;
        Of[obase + (size_t)(row0 + r0c + 1) * HD + d0 + j] = acc[1][j] * inv1;
    }
}

// ------------------- batchnorm helpers -------------------
// partial column sums of (a+b) over 256-row chunks
__global__ void col_partial(const float* __restrict__ a, const float* __restrict__ b,
                            float* __restrict__ psum, float* __restrict__ psq)
{
    int j = threadIdx.x;
    int blk = blockIdx.x;
    float s = 0.f, q = 0.f;
    for (int r = 0; r < 256; r++) {
        size_t i = (size_t)(blk * 256 + r) * HID + j;
        float v = a[i] + b[i];
        s += v; q += v * v;
    }
    psum[blk * HID + j] = s;
    psq[blk * HID + j] = q;
}

__global__ void col_finalize(const float* __restrict__ psum, const float* __restrict__ psq,
                             float* __restrict__ mean, float* __restrict__ rstd)
{
    int j = threadIdx.x;
    float s = 0.f, q = 0.f;
    #pragma unroll
    for (int b = 0; b < 16; b++) { s += psum[b * HID + j]; q += psq[b * HID + j]; }
    float m = s * (1.f / NTOK);
    float var = q * (1.f / NTOK) - m * m;
    var = fmaxf(var, 0.f);
    mean[j] = m;
    rstd[j] = rsqrtf(var + EPSBN);
}

__global__ void bn_apply(const float* __restrict__ a, const float* __restrict__ b,
                         const float* __restrict__ mean, const float* __restrict__ rstd,
                         const float* __restrict__ g, const float* __restrict__ be,
                         float* __restrict__ out)
{
    int idx = blockIdx.x * blockDim.x + threadIdx.x;
    int j = idx & (HID - 1);
    float v = a[idx] + b[idx];
    out[idx] = (v - mean[j]) * rstd[j] * g[j] + be[j];
}

// ------------------- launch -------------------
extern "C" void kernel_launch(void* const* d_in, const int* in_sizes, int n_in,
                              void* d_out, int out_size)
{
    const float* A   = (const float*)d_in[0];
    const float* h   = (const float*)d_in[1];
    const float* Wq  = (const float*)d_in[2];
    const float* bq  = (const float*)d_in[3];
    const float* Wk  = (const float*)d_in[4];
    const float* bk  = (const float*)d_in[5];
    const float* Wv  = (const float*)d_in[6];
    const float* bv  = (const float*)d_in[7];
    const float* Wo  = (const float*)d_in[8];
    const float* bo  = (const float*)d_in[9];
    const float* W1  = (const float*)d_in[10];
    const float* c1  = (const float*)d_in[11];
    const float* W2  = (const float*)d_in[12];
    const float* c2  = (const float*)d_in[13];
    const float* g1  = (const float*)d_in[14];
    const float* be1 = (const float*)d_in[15];
    const float* g2  = (const float*)d_in[16];
    const float* be2 = (const float*)d_in[17];
    float* out = (float*)d_out;

    float *Qf, *Kf, *Vf, *AO, *X, *X1, *Mid, *F, *psum, *psq, *mean, *rstd;
    cudaGetSymbolAddress((void**)&Qf,  g_Qf);
    cudaGetSymbolAddress((void**)&Kf,  g_Kf);
    cudaGetSymbolAddress((void**)&Vf,  g_Vf);
    cudaGetSymbolAddress((void**)&AO,  g_AO);
    cudaGetSymbolAddress((void**)&X,   g_X);
    cudaGetSymbolAddress((void**)&X1,  g_X1);
    cudaGetSymbolAddress((void**)&Mid, g_Mid);
    cudaGetSymbolAddress((void**)&F,   g_F);
    cudaGetSymbolAddress((void**)&psum, g_psum);
    cudaGetSymbolAddress((void**)&psq,  g_psq);
    cudaGetSymbolAddress((void**)&mean, g_mean);
    cudaGetSymbolAddress((void**)&rstd, g_rstd);

    dim3 gproj(HID / 64, NTOK / 64);       // 4 x 64
    dim3 gffn1(2 * HID / 64, NTOK / 64);   // 8 x 64
    dim3 gattn(NTOK / 64, NHEADS);         // 64 x 8

    // QKV projections (q pre-scaled by 1/sqrt(head_dim))
    gemm_nt<<<gproj, 256>>>(h, Wq, bq, Qf, NTOK, HID, HID, QSCALE, 0);
    gemm_nt<<<gproj, 256>>>(h, Wk, bk, Kf, NTOK, HID, HID, 1.f, 0);
    gemm_nt<<<gproj, 256>>>(h, Wv, bv, Vf, NTOK, HID, HID, 1.f, 0);

    // attention (flash, A folded multiplicatively into logits)
    flash_attn<<<gattn, 256>>>(Qf, Kf, Vf, A, AO);

    // output projection
    gemm_nt<<<gproj, 256>>>(AO, Wo, bo, X, NTOK, HID, HID, 1.f, 0);

    // BN1 over (X + h)
    col_partial<<<16, HID>>>(X, h, psum, psq);
    col_finalize<<<1, HID>>>(psum, psq, mean, rstd);
    bn_apply<<<NTOK * HID / 256, 256>>>(X, h, mean, rstd, g1, be1, X1);

    // FFN
    gemm_nt<<<gffn1, 256>>>(X1, W1, c1, Mid, NTOK, 2 * HID, HID, 1.f, 1);
    gemm_nt<<<gproj, 256>>>(Mid, W2, c2, F, NTOK, HID, 2 * HID, 1.f, 0);

    // BN2 over (X1 + F) -> out
    col_partial<<<16, HID>>>(X1, F, psum, psq);
    col_finalize<<<1, HID>>>(psum, psq, mean, rstd);
    bn_apply<<<NTOK * HID / 256, 256>>>(X1, F, mean, rstd, g2, be2, out);
}

// round 2
// speedup vs baseline: 2.1148x; 2.1148x over previous
#include <cuda_runtime.h>
#include <cuda_bf16.h>
#include <cstdint>

#define NTOK 4096
#define HID 256
#define NHEADS 8
#define HD 32
#define EPSBN 1e-5f
#define QSCALE 0.17677669529663687f   // 1/sqrt(32)

// ------------------- scratch (device globals; no allocation) -------------------
__device__ float g_Qf[NTOK * HID];
__device__ float g_Kf[NTOK * HID];
__device__ float g_Vf[NTOK * HID];
__device__ float g_AO[NTOK * HID];    // attention output (flat reshape layout)
__device__ float g_X[NTOK * HID];     // after O-proj
__device__ float g_X1[NTOK * HID];    // after BN1
__device__ float g_Mid[NTOK * 2 * HID];
__device__ float g_F[NTOK * HID];     // FFN output
__device__ float g_psum[16 * HID];
__device__ float g_psq[16 * HID];
__device__ float g_mean[HID];
__device__ float g_rstd[HID];

// ------------------- generic SGEMM: C = (A[M,K] @ B[N,K]^T + bias) * scale -------------------
__global__ void gemm_nt(const float* __restrict__ A, const float* __restrict__ B,
                        const float* __restrict__ bias, float* __restrict__ C,
                        int M, int Nn, int K, float scale, int relu)
{
    __shared__ float As[64][33];
    __shared__ float Bs[64][33];
    int i0 = blockIdx.y * 64, j0 = blockIdx.x * 64;
    int tid = threadIdx.x;
    int ty = tid >> 4, tx = tid & 15;
    float acc[4][4] = {};
    for (int kk = 0; kk < K; kk += 32) {
        #pragma unroll
        for (int i = tid; i < 2048; i += 256) {
            int r = i >> 5, c = i & 31;
            As[r][c] = A[(size_t)(i0 + r) * K + kk + c];
            Bs[r][c] = B[(size_t)(j0 + r) * K + kk + c];
        }
        __syncthreads();
        #pragma unroll
        for (int k = 0; k < 32; k++) {
            float a[4], b[4];
            #pragma unroll
            for (int u = 0; u < 4; u++) a[u] = As[ty * 4 + u][k];
            #pragma unroll
            for (int v = 0; v < 4; v++) b[v] = Bs[tx * 4 + v][k];
            #pragma unroll
            for (int u = 0; u < 4; u++)
                #pragma unroll
                for (int v = 0; v < 4; v++) acc[u][v] += a[u] * b[v];
        }
        __syncthreads();
    }
    #pragma unroll
    for (int u = 0; u < 4; u++)
        #pragma unroll
        for (int v = 0; v < 4; v++) {
            int i = i0 + ty * 4 + u, j = j0 + tx * 4 + v;
            float cv = (acc[u][v] + bias[j]) * scale;
            if (relu) cv = fmaxf(cv, 0.f);
            C[(size_t)i * Nn + j] = cv;
        }
}

// ------------------- tensor-core flash attention (bf16 split, mma.sync) -------------------
// S = (Q Kᵀ) ∘ A, online softmax per warp-owned rows, O = P V.
// Each input matrix x is split x = hi + lo (bf16 each); products use hi·hi + hi·lo + lo·hi.
// Block: 256 threads = 8 warps; warp owns 16 query rows. BM=128, BN=64, HD=32.

__device__ __forceinline__ void mma_bf16(float* c, const uint32_t* a, const uint32_t* b)
{
    asm volatile(
        "mma.sync.aligned.m16n8k16.row.col.f32.bf16.bf16.f32 "
        "{%0,%1,%2,%3}, {%4,%5,%6,%7}, {%8,%9}, {%0,%1,%2,%3};"
        : "+f"(c[0]), "+f"(c[1]), "+f"(c[2]), "+f"(c[3])
        : "r"(a[0]), "r"(a[1]), "r"(a[2]), "r"(a[3]), "r"(b[0]), "r"(b[1]));
}

__device__ __forceinline__ void split_pack(float x, float y, uint32_t& hi, uint32_t& lo)
{
    __nv_bfloat16 xh = __float2bfloat16_rn(x);
    __nv_bfloat16 yh = __float2bfloat16_rn(y);
    float xr = __bfloat162float(xh), yr = __bfloat162float(yh);
    __nv_bfloat16 xl = __float2bfloat16_rn(x - xr);
    __nv_bfloat16 yl = __float2bfloat16_rn(y - yr);
    __nv_bfloat162 h2; h2.x = xh; h2.y = yh;
    __nv_bfloat162 l2; l2.x = xl; l2.y = yl;
    hi = *reinterpret_cast<uint32_t*>(&h2);
    lo = *reinterpret_cast<uint32_t*>(&l2);
}

#define KPITCH 40   // bf16 elems per K-row in smem (80B: conflict-free B-frag reads)
#define VPITCH 72   // bf16 elems per Vt-row in smem (144B: conflict-free B-frag reads)

__global__ void __launch_bounds__(256, 2)
flash_attn_mma(const float* __restrict__ Qf, const float* __restrict__ Kf,
               const float* __restrict__ Vf, const float* __restrict__ Amat,
               float* __restrict__ Of)
{
    __shared__ __nv_bfloat16 Kh[64 * KPITCH];
    __shared__ __nv_bfloat16 Kl[64 * KPITCH];
    __shared__ __nv_bfloat16 Vth[HD * VPITCH];
    __shared__ __nv_bfloat16 Vtl[HD * VPITCH];

    const int tid  = threadIdx.x;
    const int w    = tid >> 5;
    const int lane = tid & 31;
    const int qr   = lane >> 2;        // 0..7
    const int qc2  = (lane & 3) * 2;   // 0,2,4,6

    const int hh   = blockIdx.y;
    const int row0 = blockIdx.x * 128;
    const int r0   = w * 16;           // warp's first query row within block

    const float* qbase = Qf + (size_t)hh * NTOK * HD;
    const float* kbase = Kf + (size_t)hh * NTOK * HD;
    const float* vbase = Vf + (size_t)hh * NTOK * HD;

    // ---- load Q fragments once (hi/lo bf16 splits), kept in registers ----
    uint32_t aQh[2][4], aQl[2][4];
    {
        const int ra = row0 + r0 + qr;
        const int rb = ra + 8;
        #pragma unroll
        for (int ks = 0; ks < 2; ks++) {
            int cb = ks * 16 + qc2;
            float2 q00 = *(const float2*)&qbase[(size_t)ra * HD + cb];
            float2 q10 = *(const float2*)&qbase[(size_t)rb * HD + cb];
            float2 q01 = *(const float2*)&qbase[(size_t)ra * HD + cb + 8];
            float2 q11 = *(const float2*)&qbase[(size_t)rb * HD + cb + 8];
            split_pack(q00.x, q00.y, aQh[ks][0], aQl[ks][0]);
            split_pack(q10.x, q10.y, aQh[ks][1], aQl[ks][1]);
            split_pack(q01.x, q01.y, aQh[ks][2], aQl[ks][2]);
            split_pack(q11.x, q11.y, aQh[ks][3], aQl[ks][3]);
        }
    }

    float oacc[4][4] = {};
    float mst0 = -3.0e38f, mst1 = -3.0e38f;
    float lst0 = 0.f, lst1 = 0.f;

    const int ga = (row0 + r0 + qr) * NTOK;       // adjacency row offsets
    const int gb = (row0 + r0 + qr + 8) * NTOK;

    for (int mt = 0; mt < NTOK / 64; mt++) {
        const int m0 = mt * 64;
        __syncthreads();
        // ---- stage K (row-major) and V (transposed) hi/lo tiles into smem ----
        #pragma unroll
        for (int j = tid; j < 512; j += 256) {
            int r = j >> 3, c4 = (j & 7) * 4;
            float4 kv = *(const float4*)&kbase[(size_t)(m0 + r) * HD + c4];
            uint32_t h01, l01, h23, l23;
            split_pack(kv.x, kv.y, h01, l01);
            split_pack(kv.z, kv.w, h23, l23);
            *(uint32_t*)&Kh[r * KPITCH + c4]     = h01;
            *(uint32_t*)&Kh[r * KPITCH + c4 + 2] = h23;
            *(uint32_t*)&Kl[r * KPITCH + c4]     = l01;
            *(uint32_t*)&Kl[r * KPITCH + c4 + 2] = l23;

            float4 vv = *(const float4*)&vbase[(size_t)(m0 + r) * HD + c4];
            float vf[4] = {vv.x, vv.y, vv.z, vv.w};
            #pragma unroll
            for (int e = 0; e < 4; e++) {
                __nv_bfloat16 vh = __float2bfloat16_rn(vf[e]);
                __nv_bfloat16 vl = __float2bfloat16_rn(vf[e] - __bfloat162float(vh));
                Vth[(c4 + e) * VPITCH + r] = vh;
                Vtl[(c4 + e) * VPITCH + r] = vl;
            }
        }
        __syncthreads();

        // ---- step A: S(16x64 per warp) = Q·Kᵀ (split: qh·kh + ql·kh + qh·kl) ----
        float sacc[8][4];
        #pragma unroll
        for (int nt = 0; nt < 8; nt++) {
            sacc[nt][0] = sacc[nt][1] = sacc[nt][2] = sacc[nt][3] = 0.f;
            #pragma unroll
            for (int ks = 0; ks < 2; ks++) {
                int off = (nt * 8 + qr) * KPITCH + ks * 16 + qc2;
                uint32_t bh[2], bl[2];
                bh[0] = *(const uint32_t*)&Kh[off];
                bh[1] = *(const uint32_t*)&Kh[off + 8];
                bl[0] = *(const uint32_t*)&Kl[off];
                bl[1] = *(const uint32_t*)&Kl[off + 8];
                mma_bf16(sacc[nt], aQh[ks], bh);
                mma_bf16(sacc[nt], aQl[ks], bh);
                mma_bf16(sacc[nt], aQh[ks], bl);
            }
        }

        // ---- multiplicative adjacency: S *= A ----
        #pragma unroll
        for (int nt = 0; nt < 8; nt++) {
            int gc = m0 + nt * 8 + qc2;
            float2 Ar = *(const float2*)&Amat[(size_t)ga + gc];
            float2 Br = *(const float2*)&Amat[(size_t)gb + gc];
            sacc[nt][0] *= Ar.x; sacc[nt][1] *= Ar.y;
            sacc[nt][2] *= Br.x; sacc[nt][3] *= Br.y;
        }

        // ---- online softmax (rows fully lane-resident: rows qr and qr+8) ----
        float mx0 = -3.0e38f, mx1 = -3.0e38f;
        #pragma unroll
        for (int nt = 0; nt < 8; nt++) {
            mx0 = fmaxf(mx0, fmaxf(sacc[nt][0], sacc[nt][1]));
            mx1 = fmaxf(mx1, fmaxf(sacc[nt][2], sacc[nt][3]));
        }
        mx0 = fmaxf(mx0, __shfl_xor_sync(0xffffffffu, mx0, 1));
        mx0 = fmaxf(mx0, __shfl_xor_sync(0xffffffffu, mx0, 2));
        mx1 = fmaxf(mx1, __shfl_xor_sync(0xffffffffu, mx1, 1));
        mx1 = fmaxf(mx1, __shfl_xor_sync(0xffffffffu, mx1, 2));

        float mn0 = fmaxf(mst0, mx0), mn1 = fmaxf(mst1, mx1);
        float al0 = __expf(mst0 - mn0), al1 = __expf(mst1 - mn1);
        mst0 = mn0; mst1 = mn1;

        float ls0 = 0.f, ls1 = 0.f;
        #pragma unroll
        for (int nt = 0; nt < 8; nt++) {
            sacc[nt][0] = __expf(sacc[nt][0] - mn0);
            sacc[nt][1] = __expf(sacc[nt][1] - mn0);
            sacc[nt][2] = __expf(sacc[nt][2] - mn1);
            sacc[nt][3] = __expf(sacc[nt][3] - mn1);
            ls0 += sacc[nt][0] + sacc[nt][1];
            ls1 += sacc[nt][2] + sacc[nt][3];
        }
        ls0 += __shfl_xor_sync(0xffffffffu, ls0, 1);
        ls0 += __shfl_xor_sync(0xffffffffu, ls0, 2);
        ls1 += __shfl_xor_sync(0xffffffffu, ls1, 1);
        ls1 += __shfl_xor_sync(0xffffffffu, ls1, 2);
        lst0 = lst0 * al0 + ls0;
        lst1 = lst1 * al1 + ls1;

        #pragma unroll
        for (int nt = 0; nt < 4; nt++) {
            oacc[nt][0] *= al0; oacc[nt][1] *= al0;
            oacc[nt][2] *= al1; oacc[nt][3] *= al1;
        }

        // ---- step C: O(16x32) += P·V (split: ph·vh + pl·vh + ph·vl) ----
        #pragma unroll
        for (int kc = 0; kc < 4; kc++) {
            uint32_t ah[4], al_[4];
            split_pack(sacc[2 * kc][0],     sacc[2 * kc][1],     ah[0], al_[0]);
            split_pack(sacc[2 * kc][2],     sacc[2 * kc][3],     ah[1], al_[1]);
            split_pack(sacc[2 * kc + 1][0], sacc[2 * kc + 1][1], ah[2], al_[2]);
            split_pack(sacc[2 * kc + 1][2], sacc[2 * kc + 1][3], ah[3], al_[3]);
            #pragma unroll
            for (int nt = 0; nt < 4; nt++) {
                int off = (nt * 8 + qr) * VPITCH + kc * 16 + qc2;
                uint32_t bh[2], bl[2];
                bh[0] = *(const uint32_t*)&Vth[off];
                bh[1] = *(const uint32_t*)&Vth[off + 8];
                bl[0] = *(const uint32_t*)&Vtl[off];
                bl[1] = *(const uint32_t*)&Vtl[off + 8];
                mma_bf16(oacc[nt], ah,  bh);
                mma_bf16(oacc[nt], al_, bh);
                mma_bf16(oacc[nt], ah,  bl);
            }
        }
    }

    // ---- epilogue: normalize and store ----
    float inv0 = 1.f / lst0, inv1 = 1.f / lst1;
    size_t obase = (size_t)hh * NTOK * HD;
    const int ra = row0 + r0 + qr;
    const int rb = ra + 8;
    #pragma unroll
    for (int nt = 0; nt < 4; nt++) {
        int c = nt * 8 + qc2;
        float2 v0 = make_float2(oacc[nt][0] * inv0, oacc[nt][1] * inv0);
        float2 v1 = make_float2(oacc[nt][2] * inv1, oacc[nt][3] * inv1);
        *(float2*)&Of[obase + (size_t)ra * HD + c] = v0;
        *(float2*)&Of[obase + (size_t)rb * HD + c] = v1;
    }
}

// ------------------- batchnorm helpers -------------------
__global__ void col_partial(const float* __restrict__ a, const float* __restrict__ b,
                            float* __restrict__ psum, float* __restrict__ psq)
{
    int j = threadIdx.x;
    int blk = blockIdx.x;
    float s = 0.f, q = 0.f;
    for (int r = 0; r < 256; r++) {
        size_t i = (size_t)(blk * 256 + r) * HID + j;
        float v = a[i] + b[i];
        s += v; q += v * v;
    }
    psum[blk * HID + j] = s;
    psq[blk * HID + j] = q;
}

__global__ void col_finalize(const float* __restrict__ psum, const float* __restrict__ psq,
                             float* __restrict__ mean, float* __restrict__ rstd)
{
    int j = threadIdx.x;
    float s = 0.f, q = 0.f;
    #pragma unroll
    for (int b = 0; b < 16; b++) { s += psum[b * HID + j]; q += psq[b * HID + j]; }
    float m = s * (1.f / NTOK);
    float var = q * (1.f / NTOK) - m * m;
    var = fmaxf(var, 0.f);
    mean[j] = m;
    rstd[j] = rsqrtf(var + EPSBN);
}

__global__ void bn_apply(const float* __restrict__ a, const float* __restrict__ b,
                         const float* __restrict__ mean, const float* __restrict__ rstd,
                         const float* __restrict__ g, const float* __restrict__ be,
                         float* __restrict__ out)
{
    int idx = blockIdx.x * blockDim.x + threadIdx.x;
    int j = idx & (HID - 1);
    float v = a[idx] + b[idx];
    out[idx] = (v - mean[j]) * rstd[j] * g[j] + be[j];
}

// ------------------- launch -------------------
extern "C" void kernel_launch(void* const* d_in, const int* in_sizes, int n_in,
                              void* d_out, int out_size)
{
    const float* A   = (const float*)d_in[0];
    const float* h   = (const float*)d_in[1];
    const float* Wq  = (const float*)d_in[2];
    const float* bq  = (const float*)d_in[3];
    const float* Wk  = (const float*)d_in[4];
    const float* bk  = (const float*)d_in[5];
    const float* Wv  = (const float*)d_in[6];
    const float* bv  = (const float*)d_in[7];
    const float* Wo  = (const float*)d_in[8];
    const float* bo  = (const float*)d_in[9];
    const float* W1  = (const float*)d_in[10];
    const float* c1  = (const float*)d_in[11];
    const float* W2  = (const float*)d_in[12];
    const float* c2  = (const float*)d_in[13];
    const float* g1  = (const float*)d_in[14];
    const float* be1 = (const float*)d_in[15];
    const float* g2  = (const float*)d_in[16];
    const float* be2 = (const float*)d_in[17];
    float* out = (float*)d_out;

    float *Qf, *Kf, *Vf, *AO, *X, *X1, *Mid, *F, *psum, *psq, *mean, *rstd;
    cudaGetSymbolAddress((void**)&Qf,  g_Qf);
    cudaGetSymbolAddress((void**)&Kf,  g_Kf);
    cudaGetSymbolAddress((void**)&Vf,  g_Vf);
    cudaGetSymbolAddress((void**)&AO,  g_AO);
    cudaGetSymbolAddress((void**)&X,   g_X);
    cudaGetSymbolAddress((void**)&X1,  g_X1);
    cudaGetSymbolAddress((void**)&Mid, g_Mid);
    cudaGetSymbolAddress((void**)&F,   g_F);
    cudaGetSymbolAddress((void**)&psum, g_psum);
    cudaGetSymbolAddress((void**)&psq,  g_psq);
    cudaGetSymbolAddress((void**)&mean, g_mean);
    cudaGetSymbolAddress((void**)&rstd, g_rstd);

    dim3 gproj(HID / 64, NTOK / 64);       // 4 x 64
    dim3 gffn1(2 * HID / 64, NTOK / 64);   // 8 x 64
    dim3 gattn(NTOK / 128, NHEADS);        // 32 x 8

    // QKV projections (q pre-scaled by 1/sqrt(head_dim))
    gemm_nt<<<gproj, 256>>>(h, Wq, bq, Qf, NTOK, HID, HID, QSCALE, 0);
    gemm_nt<<<gproj, 256>>>(h, Wk, bk, Kf, NTOK, HID, HID, 1.f, 0);
    gemm_nt<<<gproj, 256>>>(h, Wv, bv, Vf, NTOK, HID, HID, 1.f, 0);

    // attention (flash, tensor-core bf16-split, A folded multiplicatively)
    flash_attn_mma<<<gattn, 256>>>(Qf, Kf, Vf, A, AO);

    // output projection
    gemm_nt<<<gproj, 256>>>(AO, Wo, bo, X, NTOK, HID, HID, 1.f, 0);

    // BN1 over (X + h)
    col_partial<<<16, HID>>>(X, h, psum, psq);
    col_finalize<<<1, HID>>>(psum, psq, mean, rstd);
    bn_apply<<<NTOK * HID / 256, 256>>>(X, h, mean, rstd, g1, be1, X1);

    // FFN
    gemm_nt<<<gffn1, 256>>>(X1, W1, c1, Mid, NTOK, 2 * HID, HID, 1.f, 1);
    gemm_nt<<<gproj, 256>>>(Mid, W2, c2, F, NTOK, HID, 2 * HID, 1.f, 0);

    // BN2 over (X1 + F) -> out
    col_partial<<<16, HID>>>(X1, F, psum, psq);
    col_finalize<<<1, HID>>>(psum, psq, mean, rstd);
    bn_apply<<<NTOK * HID / 256, 256>>>(X1, F, mean, rstd, g2, be2, out);
}

// round 4
// speedup vs baseline: 2.6864x; 1.2703x over previous
#include <cuda_runtime.h>
#include <cuda_bf16.h>
#include <cstdint>

#define NTOK 4096
#define HID 256
#define NHEADS 8
#define HD 32
#define EPSBN 1e-5f
#define QSCALE 0.17677669529663687f   // 1/sqrt(32)

// ------------------- scratch (device globals; no allocation) -------------------
__device__ float g_Qf[NTOK * HID];
__device__ float g_Kf[NTOK * HID];
__device__ float g_Vf[NTOK * HID];
__device__ float g_AO[NTOK * HID];
__device__ float g_X[NTOK * HID];
__device__ float g_X1[NTOK * HID];
__device__ float g_Mid[NTOK * 2 * HID];
__device__ float g_F[NTOK * HID];
__device__ float g_psum[64 * HID];
__device__ float g_psq[64 * HID];
__device__ float g_mean[HID];
__device__ float g_rstd[HID];

// ------------------- helpers -------------------
__device__ __forceinline__ void mma_bf16(float* c, const uint32_t* a, const uint32_t* b)
{
    asm volatile(
        "mma.sync.aligned.m16n8k16.row.col.f32.bf16.bf16.f32 "
        "{%0,%1,%2,%3}, {%4,%5,%6,%7}, {%8,%9}, {%0,%1,%2,%3};"
        : "+f"(c[0]), "+f"(c[1]), "+f"(c[2]), "+f"(c[3])
        : "r"(a[0]), "r"(a[1]), "r"(a[2]), "r"(a[3]), "r"(b[0]), "r"(b[1]));
}

__device__ __forceinline__ void split_pack(float x, float y, uint32_t& hi, uint32_t& lo)
{
    __nv_bfloat16 xh = __float2bfloat16_rn(x);
    __nv_bfloat16 yh = __float2bfloat16_rn(y);
    float xr = __bfloat162float(xh), yr = __bfloat162float(yh);
    __nv_bfloat16 xl = __float2bfloat16_rn(x - xr);
    __nv_bfloat16 yl = __float2bfloat16_rn(y - yr);
    __nv_bfloat162 h2; h2.x = xh; h2.y = yh;
    __nv_bfloat162 l2; l2.x = xl; l2.y = yl;
    hi = *reinterpret_cast<uint32_t*>(&h2);
    lo = *reinterpret_cast<uint32_t*>(&l2);
}

__device__ __forceinline__ uint32_t scvta(const void* p)
{
    return (uint32_t)__cvta_generic_to_shared(p);
}

__device__ __forceinline__ void ldsm_x4(uint32_t* d, uint32_t addr)
{
    asm volatile("ldmatrix.sync.aligned.m8n8.x4.shared.b16 {%0,%1,%2,%3}, [%4];"
                 : "=r"(d[0]), "=r"(d[1]), "=r"(d[2]), "=r"(d[3]) : "r"(addr));
}

__device__ __forceinline__ void ldsm_x2(uint32_t* d, uint32_t addr)
{
    asm volatile("ldmatrix.sync.aligned.m8n8.x2.shared.b16 {%0,%1}, [%2];"
                 : "=r"(d[0]), "=r"(d[1]) : "r"(addr));
}

// ------------------- tensor-core GEMM: C = (A[M,K] @ W[N,K]^T + bias)*scale (opt relu) ------
// bf16 2-term split (hi+lo), 3 mma per product. Block 128x64, 8 warps, warp = 16x64.
#define GKP 40

__device__ __forceinline__ void gemm_body(
    const float* __restrict__ A, const float* __restrict__ W,
    const float* __restrict__ bias, float* __restrict__ C,
    int Nout, int K, float scale, int relu,
    __nv_bfloat16* Ah, __nv_bfloat16* Al, __nv_bfloat16* Wh, __nv_bfloat16* Wl)
{
    const int tid = threadIdx.x, w = tid >> 5, lane = tid & 31;
    const int qr = lane >> 2, qc2 = (lane & 3) * 2;
    const int i0 = blockIdx.y * 128, j0 = blockIdx.x * 64;
    const int r0 = w * 16;

    float acc[8][4] = {};

    // ldmatrix per-lane element offsets
    const int arow = r0 + ((lane >> 3) & 1) * 8 + (lane & 7);
    const int acol = (lane >> 4) * 8;                  // + ks*16
    const int brow = (lane & 7);                       // + nt*8
    const int bcol = (lane >> 3) * 8;

    const uint32_t ahb = scvta(Ah), alb = scvta(Al);
    const uint32_t whb = scvta(Wh), wlb = scvta(Wl);

    for (int kk = 0; kk < K; kk += 32) {
        #pragma unroll
        for (int t = 0; t < 4; t++) {
            int j = tid + t * 256;              // 1024 float4 covers 128x32
            int r = j >> 3, c4 = (j & 7) * 4;
            float4 av = *(const float4*)&A[(size_t)(i0 + r) * K + kk + c4];
            uint32_t h01, l01, h23, l23;
            split_pack(av.x, av.y, h01, l01);
            split_pack(av.z, av.w, h23, l23);
            *(uint32_t*)&Ah[r * GKP + c4]     = h01;
            *(uint32_t*)&Ah[r * GKP + c4 + 2] = h23;
            *(uint32_t*)&Al[r * GKP + c4]     = l01;
            *(uint32_t*)&Al[r * GKP + c4 + 2] = l23;
        }
        #pragma unroll
        for (int t = 0; t < 2; t++) {
            int j = tid + t * 256;              // 512 float4 covers 64x32
            int r = j >> 3, c4 = (j & 7) * 4;
            float4 wv = *(const float4*)&W[(size_t)(j0 + r) * K + kk + c4];
            uint32_t h01, l01, h23, l23;
            split_pack(wv.x, wv.y, h01, l01);
            split_pack(wv.z, wv.w, h23, l23);
            *(uint32_t*)&Wh[r * GKP + c4]     = h01;
            *(uint32_t*)&Wh[r * GKP + c4 + 2] = h23;
            *(uint32_t*)&Wl[r * GKP + c4]     = l01;
            *(uint32_t*)&Wl[r * GKP + c4 + 2] = l23;
        }
        __syncthreads();

        uint32_t ah[2][4], al[2][4];
        #pragma unroll
        for (int ks = 0; ks < 2; ks++) {
            uint32_t off = (uint32_t)((arow * GKP + ks * 16 + acol) * 2);
            ldsm_x4(ah[ks], ahb + off);
            ldsm_x4(al[ks], alb + off);
        }
        #pragma unroll
        for (int nt = 0; nt < 8; nt++) {
            uint32_t bh[4], bl[4];
            uint32_t off = (uint32_t)(((nt * 8 + brow) * GKP + bcol) * 2);
            ldsm_x4(bh, whb + off);
            ldsm_x4(bl, wlb + off);
            mma_bf16(acc[nt], ah[0], bh);
            mma_bf16(acc[nt], al[0], bh);
            mma_bf16(acc[nt], ah[0], bl);
            mma_bf16(acc[nt], ah[1], bh + 2);
            mma_bf16(acc[nt], al[1], bh + 2);
            mma_bf16(acc[nt], ah[1], bl + 2);
        }
        __syncthreads();
    }

    const int ra = i0 + r0 + qr, rb = ra + 8;
    #pragma unroll
    for (int nt = 0; nt < 8; nt++) {
        int j = j0 + nt * 8 + qc2;
        float b0 = bias[j], b1 = bias[j + 1];
        float v00 = (acc[nt][0] + b0) * scale;
        float v01 = (acc[nt][1] + b1) * scale;
        float v10 = (acc[nt][2] + b0) * scale;
        float v11 = (acc[nt][3] + b1) * scale;
        if (relu) {
            v00 = fmaxf(v00, 0.f); v01 = fmaxf(v01, 0.f);
            v10 = fmaxf(v10, 0.f); v11 = fmaxf(v11, 0.f);
        }
        *(float2*)&C[(size_t)ra * Nout + j] = make_float2(v00, v01);
        *(float2*)&C[(size_t)rb * Nout + j] = make_float2(v10, v11);
    }
}

__global__ void __launch_bounds__(256, 2)
gemm_one(const float* __restrict__ A, const float* __restrict__ W,
         const float* __restrict__ bias, float* __restrict__ C,
         int Nout, int K, float scale, int relu)
{
    __shared__ __nv_bfloat16 Ah[128 * GKP], Al[128 * GKP];
    __shared__ __nv_bfloat16 Wh[64 * GKP],  Wl[64 * GKP];
    gemm_body(A, W, bias, C, Nout, K, scale, relu, Ah, Al, Wh, Wl);
}

__global__ void __launch_bounds__(256, 2)
gemm_qkv(const float* __restrict__ h,
         const float* __restrict__ Wq, const float* __restrict__ bq, float* __restrict__ Q,
         const float* __restrict__ Wk, const float* __restrict__ bk, float* __restrict__ Kf,
         const float* __restrict__ Wv, const float* __restrict__ bv, float* __restrict__ V)
{
    __shared__ __nv_bfloat16 Ah[128 * GKP], Al[128 * GKP];
    __shared__ __nv_bfloat16 Wh[64 * GKP],  Wl[64 * GKP];
    const float* W; const float* b; float* C; float sc;
    if (blockIdx.z == 0)      { W = Wq; b = bq; C = Q;  sc = QSCALE; }
    else if (blockIdx.z == 1) { W = Wk; b = bk; C = Kf; sc = 1.f; }
    else                      { W = Wv; b = bv; C = V;  sc = 1.f; }
    gemm_body(h, W, b, C, HID, HID, sc, 0, Ah, Al, Wh, Wl);
}

// ------------------- tensor-core flash attention (bf16 split + ldmatrix) -------------------
#define KPITCH 40   // bf16 elems per K-row (80B): ldmatrix conflict-free
#define VPITCH 72   // bf16 elems per Vt-row (144B): ldmatrix conflict-free

__global__ void __launch_bounds__(256, 2)
flash_attn_mma(const float* __restrict__ Qf, const float* __restrict__ Kf,
               const float* __restrict__ Vf, const float* __restrict__ Amat,
               float* __restrict__ Of)
{
    __shared__ __nv_bfloat16 Kh[64 * KPITCH];
    __shared__ __nv_bfloat16 Kl[64 * KPITCH];
    __shared__ __nv_bfloat16 Vth[HD * VPITCH];
    __shared__ __nv_bfloat16 Vtl[HD * VPITCH];

    const int tid  = threadIdx.x;
    const int w    = tid >> 5;
    const int lane = tid & 31;
    const int qr   = lane >> 2;
    const int qc2  = (lane & 3) * 2;

    const int hh   = blockIdx.y;
    const int row0 = blockIdx.x * 128;
    const int r0   = w * 16;

    const float* qbase = Qf + (size_t)hh * NTOK * HD;
    const float* kbase = Kf + (size_t)hh * NTOK * HD;
    const float* vbase = Vf + (size_t)hh * NTOK * HD;

    // Q fragments (hi/lo splits), register resident
    uint32_t aQh[2][4], aQl[2][4];
    {
        const int ra = row0 + r0 + qr;
        const int rb = ra + 8;
        #pragma unroll
        for (int ks = 0; ks < 2; ks++) {
            int cb = ks * 16 + qc2;
            float2 q00 = *(const float2*)&qbase[(size_t)ra * HD + cb];
            float2 q10 = *(const float2*)&qbase[(size_t)rb * HD + cb];
            float2 q01 = *(const float2*)&qbase[(size_t)ra * HD + cb + 8];
            float2 q11 = *(const float2*)&qbase[(size_t)rb * HD + cb + 8];
            split_pack(q00.x, q00.y, aQh[ks][0], aQl[ks][0]);
            split_pack(q10.x, q10.y, aQh[ks][1], aQl[ks][1]);
            split_pack(q01.x, q01.y, aQh[ks][2], aQl[ks][2]);
            split_pack(q11.x, q11.y, aQh[ks][3], aQl[ks][3]);
        }
    }

    float oacc[4][4] = {};
    float mst0 = -3.0e38f, mst1 = -3.0e38f;
    float lst0 = 0.f, lst1 = 0.f;

    const int ga = (row0 + r0 + qr) * NTOK;
    const int gb = (row0 + r0 + qr + 8) * NTOK;

    // ldmatrix bases + per-lane offsets
    const uint32_t khb = scvta(Kh), klb = scvta(Kl);
    const uint32_t vhb = scvta(Vth), vlb = scvta(Vtl);
    const uint32_t koff = (uint32_t)(((lane & 7) * KPITCH + (lane >> 3) * 8) * 2);
    const uint32_t voff = (uint32_t)(((lane & 7) * VPITCH + ((lane >> 3) & 1) * 8) * 2);

    for (int mt = 0; mt < NTOK / 64; mt++) {
        const int m0 = mt * 64;
        __syncthreads();
        #pragma unroll
        for (int j = tid; j < 512; j += 256) {
            int r = j >> 3, c4 = (j & 7) * 4;
            float4 kv = *(const float4*)&kbase[(size_t)(m0 + r) * HD + c4];
            uint32_t h01, l01, h23, l23;
            split_pack(kv.x, kv.y, h01, l01);
            split_pack(kv.z, kv.w, h23, l23);
            *(uint32_t*)&Kh[r * KPITCH + c4]     = h01;
            *(uint32_t*)&Kh[r * KPITCH + c4 + 2] = h23;
            *(uint32_t*)&Kl[r * KPITCH + c4]     = l01;
            *(uint32_t*)&Kl[r * KPITCH + c4 + 2] = l23;

            float4 vv = *(const float4*)&vbase[(size_t)(m0 + r) * HD + c4];
            float vf[4] = {vv.x, vv.y, vv.z, vv.w};
            #pragma unroll
            for (int e = 0; e < 4; e++) {
                __nv_bfloat16 vh = __float2bfloat16_rn(vf[e]);
                __nv_bfloat16 vl = __float2bfloat16_rn(vf[e] - __bfloat162float(vh));
                Vth[(c4 + e) * VPITCH + r] = vh;
                Vtl[(c4 + e) * VPITCH + r] = vl;
            }
        }
        __syncthreads();

        // ---- S = Q·Kᵀ via ldmatrix.x4 (both k-halves in one load) ----
        float sacc[8][4];
        #pragma unroll
        for (int nt = 0; nt < 8; nt++) {
            sacc[nt][0] = sacc[nt][1] = sacc[nt][2] = sacc[nt][3] = 0.f;
            uint32_t off = koff + (uint32_t)(nt * 8 * KPITCH * 2);
            uint32_t bh[4], bl[4];
            ldsm_x4(bh, khb + off);
            ldsm_x4(bl, klb + off);
            mma_bf16(sacc[nt], aQh[0], bh);
            mma_bf16(sacc[nt], aQl[0], bh);
            mma_bf16(sacc[nt], aQh[0], bl);
            mma_bf16(sacc[nt], aQh[1], bh + 2);
            mma_bf16(sacc[nt], aQl[1], bh + 2);
            mma_bf16(sacc[nt], aQh[1], bl + 2);
        }

        // ---- multiplicative adjacency ----
        #pragma unroll
        for (int nt = 0; nt < 8; nt++) {
            int gc = m0 + nt * 8 + qc2;
            float2 Ar = *(const float2*)&Amat[(size_t)ga + gc];
            float2 Br = *(const float2*)&Amat[(size_t)gb + gc];
            sacc[nt][0] *= Ar.x; sacc[nt][1] *= Ar.y;
            sacc[nt][2] *= Br.x; sacc[nt][3] *= Br.y;
        }

        // ---- online softmax ----
        float mx0 = -3.0e38f, mx1 = -3.0e38f;
        #pragma unroll
        for (int nt = 0; nt < 8; nt++) {
            mx0 = fmaxf(mx0, fmaxf(sacc[nt][0], sacc[nt][1]));
            mx1 = fmaxf(mx1, fmaxf(sacc[nt][2], sacc[nt][3]));
        }
        mx0 = fmaxf(mx0, __shfl_xor_sync(0xffffffffu, mx0, 1));
        mx0 = fmaxf(mx0, __shfl_xor_sync(0xffffffffu, mx0, 2));
        mx1 = fmaxf(mx1, __shfl_xor_sync(0xffffffffu, mx1, 1));
        mx1 = fmaxf(mx1, __shfl_xor_sync(0xffffffffu, mx1, 2));

        float mn0 = fmaxf(mst0, mx0), mn1 = fmaxf(mst1, mx1);
        float al0 = __expf(mst0 - mn0), al1 = __expf(mst1 - mn1);
        mst0 = mn0; mst1 = mn1;

        float ls0 = 0.f, ls1 = 0.f;
        #pragma unroll
        for (int nt = 0; nt < 8; nt++) {
            sacc[nt][0] = __expf(sacc[nt][0] - mn0);
            sacc[nt][1] = __expf(sacc[nt][1] - mn0);
            sacc[nt][2] = __expf(sacc[nt][2] - mn1);
            sacc[nt][3] = __expf(sacc[nt][3] - mn1);
            ls0 += sacc[nt][0] + sacc[nt][1];
            ls1 += sacc[nt][2] + sacc[nt][3];
        }
        ls0 += __shfl_xor_sync(0xffffffffu, ls0, 1);
        ls0 += __shfl_xor_sync(0xffffffffu, ls0, 2);
        ls1 += __shfl_xor_sync(0xffffffffu, ls1, 1);
        ls1 += __shfl_xor_sync(0xffffffffu, ls1, 2);
        lst0 = lst0 * al0 + ls0;
        lst1 = lst1 * al1 + ls1;

        #pragma unroll
        for (int nt = 0; nt < 4; nt++) {
            oacc[nt][0] *= al0; oacc[nt][1] *= al0;
            oacc[nt][2] *= al1; oacc[nt][3] *= al1;
        }

        // ---- O += P·V via ldmatrix.x2 ----
        #pragma unroll
        for (int kc = 0; kc < 4; kc++) {
            uint32_t ah[4], al_[4];
            split_pack(sacc[2 * kc][0],     sacc[2 * kc][1],     ah[0], al_[0]);
            split_pack(sacc[2 * kc][2],     sacc[2 * kc][3],     ah[1], al_[1]);
            split_pack(sacc[2 * kc + 1][0], sacc[2 * kc + 1][1], ah[2], al_[2]);
            split_pack(sacc[2 * kc + 1][2], sacc[2 * kc + 1][3], ah[3], al_[3]);
            #pragma unroll
            for (int nt = 0; nt < 4; nt++) {
                uint32_t off = voff + (uint32_t)((nt * 8 * VPITCH + kc * 16) * 2);
                uint32_t bh[2], bl[2];
                ldsm_x2(bh, vhb + off);
                ldsm_x2(bl, vlb + off);
                mma_bf16(oacc[nt], ah,  bh);
                mma_bf16(oacc[nt], al_, bh);
                mma_bf16(oacc[nt], ah,  bl);
            }
        }
    }

    float inv0 = 1.f / lst0, inv1 = 1.f / lst1;
    size_t obase = (size_t)hh * NTOK * HD;
    const int ra = row0 + r0 + qr;
    const int rb = ra + 8;
    #pragma unroll
    for (int nt = 0; nt < 4; nt++) {
        int c = nt * 8 + qc2;
        *(float2*)&Of[obase + (size_t)ra * HD + c] =
            make_float2(oacc[nt][0] * inv0, oacc[nt][1] * inv0);
        *(float2*)&Of[obase + (size_t)rb * HD + c] =
            make_float2(oacc[nt][2] * inv1, oacc[nt][3] * inv1);
    }
}

// ------------------- batchnorm helpers -------------------
__global__ void col_partial(const float* __restrict__ a, const float* __restrict__ b,
                            float* __restrict__ psum, float* __restrict__ psq)
{
    int j = threadIdx.x;
    int blk = blockIdx.x;
    float s = 0.f, q = 0.f;
    #pragma unroll 4
    for (int r = 0; r < 64; r++) {
        size_t i = (size_t)(blk * 64 + r) * HID + j;
        float v = a[i] + b[i];
        s += v; q += v * v;
    }
    psum[blk * HID + j] = s;
    psq[blk * HID + j] = q;
}

__global__ void col_finalize(const float* __restrict__ psum, const float* __restrict__ psq,
                             float* __restrict__ mean, float* __restrict__ rstd)
{
    int j = threadIdx.x;
    float s = 0.f, q = 0.f;
    #pragma unroll
    for (int b = 0; b < 64; b++) { s += psum[b * HID + j]; q += psq[b * HID + j]; }
    float m = s * (1.f / NTOK);
    float var = q * (1.f / NTOK) - m * m;
    var = fmaxf(var, 0.f);
    mean[j] = m;
    rstd[j] = rsqrtf(var + EPSBN);
}

__global__ void bn_apply(const float* __restrict__ a, const float* __restrict__ b,
                         const float* __restrict__ mean, const float* __restrict__ rstd,
                         const float* __restrict__ g, const float* __restrict__ be,
                         float* __restrict__ out)
{
    int idx = blockIdx.x * blockDim.x + threadIdx.x;
    int j = idx & (HID - 1);
    float v = a[idx] + b[idx];
    out[idx] = (v - mean[j]) * rstd[j] * g[j] + be[j];
}

// ------------------- launch -------------------
extern "C" void kernel_launch(void* const* d_in, const int* in_sizes, int n_in,
                              void* d_out, int out_size)
{
    const float* A   = (const float*)d_in[0];
    const float* h   = (const float*)d_in[1];
    const float* Wq  = (const float*)d_in[2];
    const float* bq  = (const float*)d_in[3];
    const float* Wk  = (const float*)d_in[4];
    const float* bk  = (const float*)d_in[5];
    const float* Wv  = (const float*)d_in[6];
    const float* bv  = (const float*)d_in[7];
    const float* Wo  = (const float*)d_in[8];
    const float* bo  = (const float*)d_in[9];
    const float* W1  = (const float*)d_in[10];
    const float* c1  = (const float*)d_in[11];
    const float* W2  = (const float*)d_in[12];
    const float* c2  = (const float*)d_in[13];
    const float* g1  = (const float*)d_in[14];
    const float* be1 = (const float*)d_in[15];
    const float* g2  = (const float*)d_in[16];
    const float* be2 = (const float*)d_in[17];
    float* out = (float*)d_out;

    float *Qf, *Kf, *Vf, *AO, *X, *X1, *Mid, *F, *psum, *psq, *mean, *rstd;
    cudaGetSymbolAddress((void**)&Qf,  g_Qf);
    cudaGetSymbolAddress((void**)&Kf,  g_Kf);
    cudaGetSymbolAddress((void**)&Vf,  g_Vf);
    cudaGetSymbolAddress((void**)&AO,  g_AO);
    cudaGetSymbolAddress((void**)&X,   g_X);
    cudaGetSymbolAddress((void**)&X1,  g_X1);
    cudaGetSymbolAddress((void**)&Mid, g_Mid);
    cudaGetSymbolAddress((void**)&F,   g_F);
    cudaGetSymbolAddress((void**)&psum, g_psum);
    cudaGetSymbolAddress((void**)&psq,  g_psq);
    cudaGetSymbolAddress((void**)&mean, g_mean);
    cudaGetSymbolAddress((void**)&rstd, g_rstd);

    dim3 gqkv(HID / 64, NTOK / 128, 3);    // 4 x 32 x 3
    dim3 gproj(HID / 64, NTOK / 128);      // 4 x 32
    dim3 gffn1(2 * HID / 64, NTOK / 128);  // 8 x 32
    dim3 gattn(NTOK / 128, NHEADS);        // 32 x 8

    // fused QKV projections (tensor-core)
    gemm_qkv<<<gqkv, 256>>>(h, Wq, bq, Qf, Wk, bk, Kf, Wv, bv, Vf);

    // attention (flash, tensor-core bf16-split, A folded multiplicatively)
    flash_attn_mma<<<gattn, 256>>>(Qf, Kf, Vf, A, AO);

    // output projection
    gemm_one<<<gproj, 256>>>(AO, Wo, bo, X, HID, HID, 1.f, 0);

    // BN1 over (X + h)
    col_partial<<<64, HID>>>(X, h, psum, psq);
    col_finalize<<<1, HID>>>(psum, psq, mean, rstd);
    bn_apply<<<NTOK * HID / 256, 256>>>(X, h, mean, rstd, g1, be1, X1);

    // FFN
    gemm_one<<<gffn1, 256>>>(X1, W1, c1, Mid, 2 * HID, HID, 1.f, 1);
    gemm_one<<<gproj, 256>>>(Mid, W2, c2, F, HID, 2 * HID, 1.f, 0);

    // BN2 over (X1 + F) -> out
    col_partial<<<64, HID>>>(X1, F, psum, psq);
    col_finalize<<<1, HID>>>(psum, psq, mean, rstd);
    bn_apply<<<NTOK * HID / 256, 256>>>(X1, F, mean, rstd, g2, be2, out);
}

// round 5
// speedup vs baseline: 3.5315x; 1.3146x over previous
#include <cuda_runtime.h>
#include <cuda_bf16.h>
#include <cstdint>

#define NTOK 4096
#define HID 256
#define NHEADS 8
#define HD 32
#define EPSBN 1e-5f
#define QSCALE 0.17677669529663687f       // 1/sqrt(32)
#define LOG2E  1.4426950408889634f
#define QK2SCALE (QSCALE * LOG2E)         // folded so softmax uses exp2

// ------------------- scratch (device globals; no allocation) -------------------
__device__ float g_Qf[NTOK * HID];
__device__ float g_Kf[NTOK * HID];
__device__ float g_Vf[NTOK * HID];
__device__ float g_AO[NTOK * HID];
__device__ float g_X[NTOK * HID];
__device__ float g_X1[NTOK * HID];
__device__ float g_Mid[NTOK * 2 * HID];
__device__ float g_F[NTOK * HID];
__device__ float g_psum[128 * HID];
__device__ float g_psq[128 * HID];
__device__ float g_scaleC[HID];
__device__ float g_shiftC[HID];

// ------------------- helpers -------------------
__device__ __forceinline__ void mma_bf16(float* c, const uint32_t* a, const uint32_t* b)
{
    asm volatile(
        "mma.sync.aligned.m16n8k16.row.col.f32.bf16.bf16.f32 "
        "{%0,%1,%2,%3}, {%4,%5,%6,%7}, {%8,%9}, {%0,%1,%2,%3};"
        : "+f"(c[0]), "+f"(c[1]), "+f"(c[2]), "+f"(c[3])
        : "r"(a[0]), "r"(a[1]), "r"(a[2]), "r"(a[3]), "r"(b[0]), "r"(b[1]));
}

// pack {lo=x, hi=y} to bf16x2 hi; residual pair to lo. 6 instructions.
__device__ __forceinline__ void split_pack(float x, float y, uint32_t& hi, uint32_t& lo)
{
    uint32_t h;
    asm("cvt.rn.bf16x2.f32 %0, %1, %2;" : "=r"(h) : "f"(y), "f"(x));
    float xr = __uint_as_float(h << 16);
    float yr = __uint_as_float(h & 0xffff0000u);
    float xl = x - xr, yl = y - yr;
    uint32_t l;
    asm("cvt.rn.bf16x2.f32 %0, %1, %2;" : "=r"(l) : "f"(yl), "f"(xl));
    hi = h; lo = l;
}

__device__ __forceinline__ float ex2(float x)
{
    float r;
    asm("ex2.approx.ftz.f32 %0, %1;" : "=f"(r) : "f"(x));
    return r;
}

__device__ __forceinline__ uint32_t scvta(const void* p)
{
    return (uint32_t)__cvta_generic_to_shared(p);
}

__device__ __forceinline__ void ldsm_x4(uint32_t* d, uint32_t addr)
{
    asm volatile("ldmatrix.sync.aligned.m8n8.x4.shared.b16 {%0,%1,%2,%3}, [%4];"
                 : "=r"(d[0]), "=r"(d[1]), "=r"(d[2]), "=r"(d[3]) : "r"(addr));
}

__device__ __forceinline__ void ldsm_x4_t(uint32_t* d, uint32_t addr)
{
    asm volatile("ldmatrix.sync.aligned.m8n8.x4.trans.shared.b16 {%0,%1,%2,%3}, [%4];"
                 : "=r"(d[0]), "=r"(d[1]), "=r"(d[2]), "=r"(d[3]) : "r"(addr));
}

// ------------------- tensor-core GEMM: C = (A[M,K] @ W[N,K]^T + bias)*scale (opt relu) ------
#define GKP 40

__device__ __forceinline__ void gemm_body(
    const float* __restrict__ A, const float* __restrict__ W,
    const float* __restrict__ bias, float* __restrict__ C,
    int Nout, int K, float scale, int relu,
    __nv_bfloat16* Ah, __nv_bfloat16* Al, __nv_bfloat16* Wh, __nv_bfloat16* Wl)
{
    const int tid = threadIdx.x, w = tid >> 5, lane = tid & 31;
    const int qr = lane >> 2, qc2 = (lane & 3) * 2;
    const int i0 = blockIdx.y * 128, j0 = blockIdx.x * 64;
    const int r0 = w * 16;

    float acc[8][4] = {};

    const int arow = r0 + ((lane >> 3) & 1) * 8 + (lane & 7);
    const int acol = (lane >> 4) * 8;
    const int brow = (lane & 7);
    const int bcol = (lane >> 3) * 8;

    const uint32_t ahb = scvta(Ah), alb = scvta(Al);
    const uint32_t whb = scvta(Wh), wlb = scvta(Wl);

    for (int kk = 0; kk < K; kk += 32) {
        #pragma unroll
        for (int t = 0; t < 4; t++) {
            int j = tid + t * 256;
            int r = j >> 3, c4 = (j & 7) * 4;
            float4 av = *(const float4*)&A[(size_t)(i0 + r) * K + kk + c4];
            uint32_t h01, l01, h23, l23;
            split_pack(av.x, av.y, h01, l01);
            split_pack(av.z, av.w, h23, l23);
            *(uint32_t*)&Ah[r * GKP + c4]     = h01;
            *(uint32_t*)&Ah[r * GKP + c4 + 2] = h23;
            *(uint32_t*)&Al[r * GKP + c4]     = l01;
            *(uint32_t*)&Al[r * GKP + c4 + 2] = l23;
        }
        #pragma unroll
        for (int t = 0; t < 2; t++) {
            int j = tid + t * 256;
            int r = j >> 3, c4 = (j & 7) * 4;
            float4 wv = *(const float4*)&W[(size_t)(j0 + r) * K + kk + c4];
            uint32_t h01, l01, h23, l23;
            split_pack(wv.x, wv.y, h01, l01);
            split_pack(wv.z, wv.w, h23, l23);
            *(uint32_t*)&Wh[r * GKP + c4]     = h01;
            *(uint32_t*)&Wh[r * GKP + c4 + 2] = h23;
            *(uint32_t*)&Wl[r * GKP + c4]     = l01;
            *(uint32_t*)&Wl[r * GKP + c4 + 2] = l23;
        }
        __syncthreads();

        uint32_t ah[2][4], al[2][4];
        #pragma unroll
        for (int ks = 0; ks < 2; ks++) {
            uint32_t off = (uint32_t)((arow * GKP + ks * 16 + acol) * 2);
            ldsm_x4(ah[ks], ahb + off);
            ldsm_x4(al[ks], alb + off);
        }
        #pragma unroll
        for (int nt = 0; nt < 8; nt++) {
            uint32_t bh[4], bl[4];
            uint32_t off = (uint32_t)(((nt * 8 + brow) * GKP + bcol) * 2);
            ldsm_x4(bh, whb + off);
            ldsm_x4(bl, wlb + off);
            mma_bf16(acc[nt], ah[0], bh);
            mma_bf16(acc[nt], al[0], bh);
            mma_bf16(acc[nt], ah[0], bl);
            mma_bf16(acc[nt], ah[1], bh + 2);
            mma_bf16(acc[nt], al[1], bh + 2);
            mma_bf16(acc[nt], ah[1], bl + 2);
        }
        __syncthreads();
    }

    const int ra = i0 + r0 + qr, rb = ra + 8;
    #pragma unroll
    for (int nt = 0; nt < 8; nt++) {
        int j = j0 + nt * 8 + qc2;
        float b0 = bias[j], b1 = bias[j + 1];
        float v00 = (acc[nt][0] + b0) * scale;
        float v01 = (acc[nt][1] + b1) * scale;
        float v10 = (acc[nt][2] + b0) * scale;
        float v11 = (acc[nt][3] + b1) * scale;
        if (relu) {
            v00 = fmaxf(v00, 0.f); v01 = fmaxf(v01, 0.f);
            v10 = fmaxf(v10, 0.f); v11 = fmaxf(v11, 0.f);
        }
        *(float2*)&C[(size_t)ra * Nout + j] = make_float2(v00, v01);
        *(float2*)&C[(size_t)rb * Nout + j] = make_float2(v10, v11);
    }
}

__global__ void __launch_bounds__(256, 2)
gemm_one(const float* __restrict__ A, const float* __restrict__ W,
         const float* __restrict__ bias, float* __restrict__ C,
         int Nout, int K, float scale, int relu)
{
    __shared__ __align__(16) __nv_bfloat16 Ah[128 * GKP], Al[128 * GKP];
    __shared__ __align__(16) __nv_bfloat16 Wh[64 * GKP],  Wl[64 * GKP];
    gemm_body(A, W, bias, C, Nout, K, scale, relu, Ah, Al, Wh, Wl);
}

__global__ void __launch_bounds__(256, 2)
gemm_qkv(const float* __restrict__ h,
         const float* __restrict__ Wq, const float* __restrict__ bq, float* __restrict__ Q,
         const float* __restrict__ Wk, const float* __restrict__ bk, float* __restrict__ Kf,
         const float* __restrict__ Wv, const float* __restrict__ bv, float* __restrict__ V)
{
    __shared__ __align__(16) __nv_bfloat16 Ah[128 * GKP], Al[128 * GKP];
    __shared__ __align__(16) __nv_bfloat16 Wh[64 * GKP],  Wl[64 * GKP];
    const float* W; const float* b; float* C; float sc;
    if (blockIdx.z == 0)      { W = Wq; b = bq; C = Q;  sc = QK2SCALE; }
    else if (blockIdx.z == 1) { W = Wk; b = bk; C = Kf; sc = 1.f; }
    else                      { W = Wv; b = bv; C = V;  sc = 1.f; }
    gemm_body(h, W, b, C, HID, HID, sc, 0, Ah, Al, Wh, Wl);
}

// ------------------- tensor-core flash attention -------------------
// No online max (scores bounded; exp2 with log2e folded into Q scale).
// K and V both staged row-major (pitch 80B); V fragments via ldmatrix.x4.trans.
#define KPITCH 40

__global__ void __launch_bounds__(256, 2)
flash_attn_mma(const float* __restrict__ Qf, const float* __restrict__ Kf,
               const float* __restrict__ Vf, const float* __restrict__ Amat,
               float* __restrict__ Of)
{
    __shared__ __align__(16) __nv_bfloat16 Kh[64 * KPITCH], Kl[64 * KPITCH];
    __shared__ __align__(16) __nv_bfloat16 Vh[64 * KPITCH], Vl[64 * KPITCH];

    const int tid  = threadIdx.x;
    const int w    = tid >> 5;
    const int lane = tid & 31;
    const int qr   = lane >> 2;
    const int qc2  = (lane & 3) * 2;

    const int hh   = blockIdx.y;
    const int row0 = blockIdx.x * 128;
    const int r0   = w * 16;

    const float* qbase = Qf + (size_t)hh * NTOK * HD;
    const float* kbase = Kf + (size_t)hh * NTOK * HD;
    const float* vbase = Vf + (size_t)hh * NTOK * HD;

    // Q fragments (hi/lo splits), register resident; Q already carries qscale*log2e
    uint32_t aQh[2][4], aQl[2][4];
    {
        const int ra = row0 + r0 + qr;
        const int rb = ra + 8;
        #pragma unroll
        for (int ks = 0; ks < 2; ks++) {
            int cb = ks * 16 + qc2;
            float2 q00 = *(const float2*)&qbase[(size_t)ra * HD + cb];
            float2 q10 = *(const float2*)&qbase[(size_t)rb * HD + cb];
            float2 q01 = *(const float2*)&qbase[(size_t)ra * HD + cb + 8];
            float2 q11 = *(const float2*)&qbase[(size_t)rb * HD + cb + 8];
            split_pack(q00.x, q00.y, aQh[ks][0], aQl[ks][0]);
            split_pack(q10.x, q10.y, aQh[ks][1], aQl[ks][1]);
            split_pack(q01.x, q01.y, aQh[ks][2], aQl[ks][2]);
            split_pack(q11.x, q11.y, aQh[ks][3], aQl[ks][3]);
        }
    }

    float oacc[4][4] = {};
    float ls0 = 0.f, ls1 = 0.f;

    const int ga = (row0 + r0 + qr) * NTOK;
    const int gb = (row0 + r0 + qr + 8) * NTOK;

    const uint32_t khb = scvta(Kh), klb = scvta(Kl);
    const uint32_t vhb = scvta(Vh), vlb = scvta(Vl);
    const uint32_t koff = (uint32_t)(((lane & 7) * KPITCH + (lane >> 3) * 8) * 2);
    const uint32_t vtoff = (uint32_t)(lane * KPITCH * 2);    // x4.trans: lane = token row

    for (int mt = 0; mt < NTOK / 64; mt++) {
        const int m0 = mt * 64;
        __syncthreads();
        // ---- stage K and V (both row-major, hi/lo split) ----
        #pragma unroll
        for (int t = 0; t < 2; t++) {
            int j = tid + t * 256;
            int r = j >> 3, c4 = (j & 7) * 4;
            float4 kv = *(const float4*)&kbase[(size_t)(m0 + r) * HD + c4];
            uint32_t h01, l01, h23, l23;
            split_pack(kv.x, kv.y, h01, l01);
            split_pack(kv.z, kv.w, h23, l23);
            *(uint32_t*)&Kh[r * KPITCH + c4]     = h01;
            *(uint32_t*)&Kh[r * KPITCH + c4 + 2] = h23;
            *(uint32_t*)&Kl[r * KPITCH + c4]     = l01;
            *(uint32_t*)&Kl[r * KPITCH + c4 + 2] = l23;
        }
        #pragma unroll
        for (int t = 0; t < 2; t++) {
            int j = tid + t * 256;
            int r = j >> 3, c4 = (j & 7) * 4;
            float4 vv = *(const float4*)&vbase[(size_t)(m0 + r) * HD + c4];
            uint32_t h01, l01, h23, l23;
            split_pack(vv.x, vv.y, h01, l01);
            split_pack(vv.z, vv.w, h23, l23);
            *(uint32_t*)&Vh[r * KPITCH + c4]     = h01;
            *(uint32_t*)&Vh[r * KPITCH + c4 + 2] = h23;
            *(uint32_t*)&Vl[r * KPITCH + c4]     = l01;
            *(uint32_t*)&Vl[r * KPITCH + c4 + 2] = l23;
        }
        __syncthreads();

        // ---- prefetch adjacency rows (overlaps with QK mma) ----
        float2 Ar[8], Br[8];
        #pragma unroll
        for (int nt = 0; nt < 8; nt++) {
            int gc = m0 + nt * 8 + qc2;
            Ar[nt] = *(const float2*)&Amat[(size_t)ga + gc];
            Br[nt] = *(const float2*)&Amat[(size_t)gb + gc];
        }

        // ---- S = Q·Kᵀ ----
        float sacc[8][4];
        #pragma unroll
        for (int nt = 0; nt < 8; nt++) {
            sacc[nt][0] = sacc[nt][1] = sacc[nt][2] = sacc[nt][3] = 0.f;
            uint32_t off = koff + (uint32_t)(nt * 8 * KPITCH * 2);
            uint32_t bh[4], bl[4];
            ldsm_x4(bh, khb + off);
            ldsm_x4(bl, klb + off);
            mma_bf16(sacc[nt], aQh[0], bh);
            mma_bf16(sacc[nt], aQl[0], bh);
            mma_bf16(sacc[nt], aQh[0], bl);
            mma_bf16(sacc[nt], aQh[1], bh + 2);
            mma_bf16(sacc[nt], aQl[1], bh + 2);
            mma_bf16(sacc[nt], aQh[1], bl + 2);
        }

        // ---- p = exp2(s * A); accumulate row sums lane-locally ----
        #pragma unroll
        for (int nt = 0; nt < 8; nt++) {
            sacc[nt][0] = ex2(sacc[nt][0] * Ar[nt].x);
            sacc[nt][1] = ex2(sacc[nt][1] * Ar[nt].y);
            sacc[nt][2] = ex2(sacc[nt][2] * Br[nt].x);
            sacc[nt][3] = ex2(sacc[nt][3] * Br[nt].y);
            ls0 += sacc[nt][0] + sacc[nt][1];
            ls1 += sacc[nt][2] + sacc[nt][3];
        }

        // ---- split P into bf16 hi/lo a-frags ----
        uint32_t ph[4][4], pl_[4][4];
        #pragma unroll
        for (int kc = 0; kc < 4; kc++) {
            split_pack(sacc[2 * kc][0],     sacc[2 * kc][1],     ph[kc][0], pl_[kc][0]);
            split_pack(sacc[2 * kc][2],     sacc[2 * kc][3],     ph[kc][1], pl_[kc][1]);
            split_pack(sacc[2 * kc + 1][0], sacc[2 * kc + 1][1], ph[kc][2], pl_[kc][2]);
            split_pack(sacc[2 * kc + 1][2], sacc[2 * kc + 1][3], ph[kc][3], pl_[kc][3]);
        }

        // ---- O += P·V via ldmatrix.x4.trans ----
        #pragma unroll
        for (int nt = 0; nt < 4; nt++) {
            uint32_t off = vtoff + (uint32_t)(nt * 16);      // nt*8 cols * 2B
            uint32_t bh[8], bl[8];
            ldsm_x4_t(bh,     vhb + off);
            ldsm_x4_t(bh + 4, vhb + off + 32 * KPITCH * 2);
            ldsm_x4_t(bl,     vlb + off);
            ldsm_x4_t(bl + 4, vlb + off + 32 * KPITCH * 2);
            #pragma unroll
            for (int kc = 0; kc < 4; kc++) {
                mma_bf16(oacc[nt], ph[kc],  bh + kc * 2);
                mma_bf16(oacc[nt], pl_[kc], bh + kc * 2);
                mma_bf16(oacc[nt], ph[kc],  bl + kc * 2);
            }
        }
    }

    // ---- final row-sum reduce + normalize ----
    ls0 += __shfl_xor_sync(0xffffffffu, ls0, 1);
    ls0 += __shfl_xor_sync(0xffffffffu, ls0, 2);
    ls1 += __shfl_xor_sync(0xffffffffu, ls1, 1);
    ls1 += __shfl_xor_sync(0xffffffffu, ls1, 2);
    float inv0 = 1.f / ls0, inv1 = 1.f / ls1;

    size_t obase = (size_t)hh * NTOK * HD;
    const int ra = row0 + r0 + qr;
    const int rb = ra + 8;
    #pragma unroll
    for (int nt = 0; nt < 4; nt++) {
        int c = nt * 8 + qc2;
        *(float2*)&Of[obase + (size_t)ra * HD + c] =
            make_float2(oacc[nt][0] * inv0, oacc[nt][1] * inv0);
        *(float2*)&Of[obase + (size_t)rb * HD + c] =
            make_float2(oacc[nt][2] * inv1, oacc[nt][3] * inv1);
    }
}

// ------------------- batchnorm helpers -------------------
__global__ void col_partial(const float* __restrict__ a, const float* __restrict__ b,
                            float* __restrict__ psum, float* __restrict__ psq)
{
    int j = threadIdx.x;
    int blk = blockIdx.x;
    float s = 0.f, q = 0.f;
    #pragma unroll 4
    for (int r = 0; r < 32; r++) {
        size_t i = (size_t)(blk * 32 + r) * HID + j;
        float v = a[i] + b[i];
        s += v; q += v * v;
    }
    psum[blk * HID + j] = s;
    psq[blk * HID + j] = q;
}

// emits fused affine coefficients: out = v*scaleC + shiftC
__global__ void col_finalize(const float* __restrict__ psum, const float* __restrict__ psq,
                             const float* __restrict__ g, const float* __restrict__ be,
                             float* __restrict__ scaleC, float* __restrict__ shiftC)
{
    int j = threadIdx.x;
    float s = 0.f, q = 0.f;
    #pragma unroll
    for (int b = 0; b < 128; b++) { s += psum[b * HID + j]; q += psq[b * HID + j]; }
    float m = s * (1.f / NTOK);
    float var = q * (1.f / NTOK) - m * m;
    var = fmaxf(var, 0.f);
    float sc = rsqrtf(var + EPSBN) * g[j];
    scaleC[j] = sc;
    shiftC[j] = be[j] - m * sc;
}

__global__ void bn_apply(const float* __restrict__ a, const float* __restrict__ b,
                         const float* __restrict__ scaleC, const float* __restrict__ shiftC,
                         float* __restrict__ out)
{
    int idx = (blockIdx.x * blockDim.x + threadIdx.x) * 4;
    int j = idx & (HID - 1);
    float4 av = *(const float4*)&a[idx];
    float4 bv = *(const float4*)&b[idx];
    float4 sc = *(const float4*)&scaleC[j];
    float4 sh = *(const float4*)&shiftC[j];
    float4 ov;
    ov.x = (av.x + bv.x) * sc.x + sh.x;
    ov.y = (av.y + bv.y) * sc.y + sh.y;
    ov.z = (av.z + bv.z) * sc.z + sh.z;
    ov.w = (av.w + bv.w) * sc.w + sh.w;
    *(float4*)&out[idx] = ov;
}

// ------------------- launch -------------------
extern "C" void kernel_launch(void* const* d_in, const int* in_sizes, int n_in,
                              void* d_out, int out_size)
{
    const float* A   = (const float*)d_in[0];
    const float* h   = (const float*)d_in[1];
    const float* Wq  = (const float*)d_in[2];
    const float* bq  = (const float*)d_in[3];
    const float* Wk  = (const float*)d_in[4];
    const float* bk  = (const float*)d_in[5];
    const float* Wv  = (const float*)d_in[6];
    const float* bv  = (const float*)d_in[7];
    const float* Wo  = (const float*)d_in[8];
    const float* bo  = (const float*)d_in[9];
    const float* W1  = (const float*)d_in[10];
    const float* c1  = (const float*)d_in[11];
    const float* W2  = (const float*)d_in[12];
    const float* c2  = (const float*)d_in[13];
    const float* g1  = (const float*)d_in[14];
    const float* be1 = (const float*)d_in[15];
    const float* g2  = (const float*)d_in[16];
    const float* be2 = (const float*)d_in[17];
    float* out = (float*)d_out;

    float *Qf, *Kf, *Vf, *AO, *X, *X1, *Mid, *F, *psum, *psq, *scaleC, *shiftC;
    cudaGetSymbolAddress((void**)&Qf,  g_Qf);
    cudaGetSymbolAddress((void**)&Kf,  g_Kf);
    cudaGetSymbolAddress((void**)&Vf,  g_Vf);
    cudaGetSymbolAddress((void**)&AO,  g_AO);
    cudaGetSymbolAddress((void**)&X,   g_X);
    cudaGetSymbolAddress((void**)&X1,  g_X1);
    cudaGetSymbolAddress((void**)&Mid, g_Mid);
    cudaGetSymbolAddress((void**)&F,   g_F);
    cudaGetSymbolAddress((void**)&psum,   g_psum);
    cudaGetSymbolAddress((void**)&psq,    g_psq);
    cudaGetSymbolAddress((void**)&scaleC, g_scaleC);
    cudaGetSymbolAddress((void**)&shiftC, g_shiftC);

    dim3 gqkv(HID / 64, NTOK / 128, 3);
    dim3 gproj(HID / 64, NTOK / 128);
    dim3 gffn1(2 * HID / 64, NTOK / 128);
    dim3 gattn(NTOK / 128, NHEADS);

    // fused QKV projections (Q carries qscale*log2e)
    gemm_qkv<<<gqkv, 256>>>(h, Wq, bq, Qf, Wk, bk, Kf, Wv, bv, Vf);

    // flash attention
    flash_attn_mma<<<gattn, 256>>>(Qf, Kf, Vf, A, AO);

    // output projection
    gemm_one<<<gproj, 256>>>(AO, Wo, bo, X, HID, HID, 1.f, 0);

    // BN1 over (X + h)
    col_partial<<<128, HID>>>(X, h, psum, psq);
    col_finalize<<<1, HID>>>(psum, psq, g1, be1, scaleC, shiftC);
    bn_apply<<<NTOK * HID / 1024, 256>>>(X, h, scaleC, shiftC, X1);

    // FFN
    gemm_one<<<gffn1, 256>>>(X1, W1, c1, Mid, 2 * HID, HID, 1.f, 1);
    gemm_one<<<gproj, 256>>>(Mid, W2, c2, F, HID, 2 * HID, 1.f, 0);

    // BN2 over (X1 + F) -> out
    col_partial<<<128, HID>>>(X1, F, psum, psq);
    col_finalize<<<1, HID>>>(psum, psq, g2, be2, scaleC, shiftC);
    bn_apply<<<NTOK * HID / 1024, 256>>>(X1, F, scaleC, shiftC, out);
}